// round 15
// baseline (speedup 1.0000x reference)
#include <cuda_runtime.h>
#include <cuda_bf16.h>
#include <cuda_fp16.h>
#include <math.h>
#include <stdint.h>

// ---------------- problem constants ----------------
#define TT   100
#define BB   512
#define WW   18
#define CC   32
#define FF   576
#define HH   128
#define GG   512
#define NC   12

// ---------------- device scratch ----------------
__device__ __half g_xp [TT * BB * GG];          // fp16 gate preacts
__device__ float g_h2  [TT * BB * HH];
__device__ float g_attn [TT * BB];
__device__ float g_pooled[BB * HH];
__device__ __nv_bfloat16 g_Ahi[TT * BB * FF];
__device__ __nv_bfloat16 g_W0hi[GG * FF], g_W0lo[GG * FF];
__device__ __nv_bfloat16 g_W1hi[GG * HH], g_W1lo[GG * HH];
__device__ __nv_bfloat16 g_Wahi[HH * HH], g_Walo[HH * HH];

// fast activations (EX2/RCP approx)
__device__ __forceinline__ float ftanh(float x) {
    float xc = fminf(fmaxf(x, -9.0f), 9.0f);
    float t = __expf(2.0f * xc);
    return __fdividef(t - 1.0f, t + 1.0f);
}
__device__ __forceinline__ float fsig(float x) {
    return __fdividef(1.0f, 1.0f + __expf(-x));
}

// packed f32x2 helpers
__device__ __forceinline__ void ffma2(unsigned long long& acc, unsigned long long a,
                                      unsigned long long b) {
    asm("fma.rn.f32x2 %0, %1, %2, %0;" : "+l"(acc) : "l"(a), "l"(b));
}
__device__ __forceinline__ unsigned long long packf2(float lo, float hi) {
    unsigned long long r;
    asm("mov.b64 %0, {%1,%2};" : "=l"(r) : "f"(lo), "f"(hi));
    return r;
}
__device__ __forceinline__ float2 unpackf2(unsigned long long v) {
    float2 r;
    asm("mov.b64 {%0,%1}, %2;" : "=f"(r.x), "=f"(r.y) : "l"(v));
    return r;
}

__device__ __forceinline__ uint32_t smem_u32(const void* p) {
    uint32_t a;
    asm("{ .reg .u64 t; cvta.to.shared.u64 t, %1; cvt.u32.u64 %0, t; }" : "=r"(a) : "l"(p));
    return a;
}
__device__ __forceinline__ void ldmat4(uint32_t* r, uint32_t addr) {
    asm volatile("ldmatrix.sync.aligned.m8n8.x4.shared.b16 {%0,%1,%2,%3}, [%4];"
                 : "=r"(r[0]), "=r"(r[1]), "=r"(r[2]), "=r"(r[3]) : "r"(addr));
}
__device__ __forceinline__ void mma16816(float* c, const uint32_t* a, const uint32_t* b) {
    asm volatile(
        "mma.sync.aligned.m16n8k16.row.col.f32.bf16.bf16.f32 "
        "{%0,%1,%2,%3}, {%4,%5,%6,%7}, {%8,%9}, {%0,%1,%2,%3};"
        : "+f"(c[0]), "+f"(c[1]), "+f"(c[2]), "+f"(c[3])
        : "r"(a[0]), "r"(a[1]), "r"(a[2]), "r"(a[3]), "r"(b[0]), "r"(b[1]));
}
__device__ __forceinline__ void split1(float v, __nv_bfloat16& h, __nv_bfloat16& l) {
    h = __float2bfloat16(v);
    l = __float2bfloat16(v - __bfloat162float(h));
}

// =====================================================================
// Weight prep: 3 launches (conv stays at ncu slot #4)
// =====================================================================
#define N4_W0 (GG * FF / 4)
#define N4_W1 (GG * HH / 4)
#define N4_WA (HH * HH / 4)
__global__ void __launch_bounds__(256) prep_a(const float* __restrict__ Wih0) {
    int i = blockIdx.x * 256 + threadIdx.x;
    if (i >= N4_W0) return;
    float4 v = ((const float4*)Wih0)[i];
    __nv_bfloat16 h0, h1, h2, h3, l0, l1, l2, l3;
    split1(v.x, h0, l0); split1(v.y, h1, l1);
    split1(v.z, h2, l2); split1(v.w, h3, l3);
    ((__nv_bfloat162*)g_W0hi)[2 * i]     = __nv_bfloat162(h0, h1);
    ((__nv_bfloat162*)g_W0hi)[2 * i + 1] = __nv_bfloat162(h2, h3);
    ((__nv_bfloat162*)g_W0lo)[2 * i]     = __nv_bfloat162(l0, l1);
    ((__nv_bfloat162*)g_W0lo)[2 * i + 1] = __nv_bfloat162(l2, l3);
}
__global__ void __launch_bounds__(256) prep_b(const float* __restrict__ Wih1) {
    int i = blockIdx.x * 256 + threadIdx.x;
    if (i >= N4_W1) return;
    float4 v = ((const float4*)Wih1)[i];
    __nv_bfloat16 h0, h1, h2, h3, l0, l1, l2, l3;
    split1(v.x, h0, l0); split1(v.y, h1, l1);
    split1(v.z, h2, l2); split1(v.w, h3, l3);
    ((__nv_bfloat162*)g_W1hi)[2 * i]     = __nv_bfloat162(h0, h1);
    ((__nv_bfloat162*)g_W1hi)[2 * i + 1] = __nv_bfloat162(h2, h3);
    ((__nv_bfloat162*)g_W1lo)[2 * i]     = __nv_bfloat162(l0, l1);
    ((__nv_bfloat162*)g_W1lo)[2 * i + 1] = __nv_bfloat162(l2, l3);
}
__global__ void __launch_bounds__(256) prep_c(const float* __restrict__ W_att) {
    int i = blockIdx.x * 256 + threadIdx.x;
    if (i >= N4_WA) return;
    int j = i * 4;
#pragma unroll
    for (int e = 0; e < 4; e++) {
        int idx = j + e;
        int c = idx >> 7, r = idx & 127;
        float v = W_att[r * HH + c];
        __nv_bfloat16 h, l;
        split1(v, h, l);
        g_Wahi[idx] = h;
        g_Walo[idx] = l;
    }
}

// =====================================================================
// Conv: ROUND-12 version. One block per image, 127KB smem, minBlocks=1
// (the ", 1" is load-bearing: without it ptxas caps at 64 regs and
// spills wr[100] to local — round-14's +456us regression).
// =====================================================================
__global__ void __launch_bounds__(256, 1) conv_kernel(const float* __restrict__ x,
                                                      const float* __restrict__ cw,
                                                      const float* __restrict__ cb) {
    extern __shared__ float s_img[];
    int b = blockIdx.x;
    int tid = threadIdx.x;
    int wid = tid >> 5, lane = tid & 31;
    int c = lane;

    const float4* src = (const float4*)(x + (size_t)b * 812 * 40);
    float4* dst = (float4*)s_img;
    for (int i = tid; i < 812 * 10; i += 256) dst[i] = src[i];

    float wr[100];
#pragma unroll
    for (int i = 0; i < 100; i++) wr[i] = __ldg(&cw[c * 100 + i]);
    float bv = __ldg(&cb[c]);
    __syncthreads();

    for (int p = wid; p < 50; p += 8) {
        int base_row = 16 * p;
        float acc[2][18];
#pragma unroll
        for (int w = 0; w < 18; w++) { acc[0][w] = bv; acc[1][w] = bv; }
#pragma unroll
        for (int rr = 0; rr < 28; rr++) {
            const float4* prow4 = (const float4*)&s_img[(base_row + rr) * 40];
#pragma unroll
            for (int j4 = 0; j4 < 10; j4++) {
                float4 pj = prow4[j4];
                float pv4[4] = {pj.x, pj.y, pj.z, pj.w};
#pragma unroll
                for (int e = 0; e < 4; e++) {
                    int j = 4 * j4 + e;
                    float pv = pv4[e];
#pragma unroll
                    for (int kw = 0; kw < 5; kw++) {
                        int d = j - kw;
                        if (d >= 0 && (d & 1) == 0) {
                            int w = d >> 1;
                            if (w < 18) {
                                if (rr < 20) acc[0][w] += wr[rr * 5 + kw] * pv;
                                if (rr >= 8) acc[1][w] += wr[(rr - 8) * 5 + kw] * pv;
                            }
                        }
                    }
                }
            }
        }
#pragma unroll
        for (int ts = 0; ts < 2; ts++) {
            int t = 2 * p + ts;
            size_t base = ((size_t)t * BB + b) * FF + c;
#pragma unroll
            for (int w = 0; w < 18; w++)
                g_Ahi[base + w * 32] = __float2bfloat16(fmaxf(acc[ts][w], 0.0f));
        }
    }
}

// =====================================================================
// 2-term GEMM: C(fp16) = Ahi@(Bhi+Blo)^T + bias. mma.sync, dbl-buffered.
// =====================================================================
#define ASTR 40
#define GTILE (128 * ASTR * 2)
#define GBUF  (3 * GTILE)
#define GSMEM (2 * GBUF)

__global__ void __launch_bounds__(256) gemm_mma(const __nv_bfloat16* __restrict__ Ahi,
                                                const __nv_bfloat16* __restrict__ Bhi,
                                                const __nv_bfloat16* __restrict__ Blo,
                                                const float* __restrict__ bias0,
                                                const float* __restrict__ bias1,
                                                __half* __restrict__ C,
                                                int M, int N, int K) {
    extern __shared__ char gsm[];
    int tid = threadIdx.x;
    int warp = tid >> 5, lane = tid & 31;
    int wm = warp >> 2, wn = warp & 3;
    int bm = blockIdx.y * 128, bn = blockIdx.x * 128;

    int lrow0 = tid >> 1;
    int lseg0 = (tid & 1) * 2;
    const __nv_bfloat16* pAhi = Ahi + (size_t)(bm + lrow0) * K + lseg0 * 8;
    const __nv_bfloat16* pBhi = Bhi + (size_t)(bn + lrow0) * K + lseg0 * 8;
    const __nv_bfloat16* pBlo = Blo + (size_t)(bn + lrow0) * K + lseg0 * 8;

    float acc[4][4][4];
#pragma unroll
    for (int i = 0; i < 4; i++)
#pragma unroll
        for (int j = 0; j < 4; j++)
#pragma unroll
            for (int q = 0; q < 4; q++) acc[i][j][q] = 0.0f;

    uint32_t sb = smem_u32(gsm);
    uint32_t stoff = (uint32_t)(lrow0 * ASTR + lseg0 * 8) * 2;

    uint32_t aRow = (uint32_t)(wm * 64 + (lane & 15));
    uint32_t aColHalf = (uint32_t)((lane >> 4) * 8);
    uint32_t g = (uint32_t)(lane >> 3);
    uint32_t bRow = (uint32_t)(wn * 32 + ((g >> 1) * 8) + (lane & 7));
    uint32_t bColHalf = (g & 1) * 8;

    uint4 ra0, ra1, rc0, rc1, rd0, rd1;
    ra0 = *(const uint4*)pAhi;       ra1 = *(const uint4*)(pAhi + 8);
    rc0 = *(const uint4*)pBhi;       rc1 = *(const uint4*)(pBhi + 8);
    rd0 = *(const uint4*)pBlo;       rd1 = *(const uint4*)(pBlo + 8);

    {
        char* b0 = gsm + stoff;
        *(uint4*)(b0 + 0 * GTILE) = ra0; *(uint4*)(b0 + 0 * GTILE + 16) = ra1;
        *(uint4*)(b0 + 1 * GTILE) = rc0; *(uint4*)(b0 + 1 * GTILE + 16) = rc1;
        *(uint4*)(b0 + 2 * GTILE) = rd0; *(uint4*)(b0 + 2 * GTILE + 16) = rd1;
    }
    __syncthreads();

    int nchunks = K >> 5;
    uint32_t cur = 0;
    for (int c0 = 0; c0 < nchunks; c0++) {
        bool more = (c0 + 1) < nchunks;
        if (more) {
            int kn = (c0 + 1) << 5;
            ra0 = *(const uint4*)(pAhi + kn);  ra1 = *(const uint4*)(pAhi + kn + 8);
            rc0 = *(const uint4*)(pBhi + kn);  rc1 = *(const uint4*)(pBhi + kn + 8);
            rd0 = *(const uint4*)(pBlo + kn);  rd1 = *(const uint4*)(pBlo + kn + 8);
        }

        uint32_t base = sb + cur * GBUF;
#pragma unroll
        for (int ko = 0; ko < 32; ko += 16) {
            uint32_t fahi[4][4], fbhi[2][4], fblo[2][4];
#pragma unroll
            for (int mi = 0; mi < 4; mi++) {
                uint32_t off = ((aRow + mi * 16) * ASTR + ko + aColHalf) * 2;
                ldmat4(fahi[mi], base + 0 * GTILE + off);
            }
#pragma unroll
            for (int np = 0; np < 2; np++) {
                uint32_t off = ((bRow + np * 16) * ASTR + ko + bColHalf) * 2;
                ldmat4(fbhi[np], base + 1 * GTILE + off);
                ldmat4(fblo[np], base + 2 * GTILE + off);
            }
#pragma unroll
            for (int mi = 0; mi < 4; mi++) {
#pragma unroll
                for (int nt = 0; nt < 4; nt++) {
                    int np = nt >> 1, hf = (nt & 1) * 2;
                    uint32_t bh[2] = { fbhi[np][hf], fbhi[np][hf + 1] };
                    uint32_t bl[2] = { fblo[np][hf], fblo[np][hf + 1] };
                    mma16816(acc[mi][nt], fahi[mi], bh);
                    mma16816(acc[mi][nt], fahi[mi], bl);
                }
            }
        }

        if (more) {
            char* bn2 = gsm + (cur ^ 1u) * GBUF + stoff;
            *(uint4*)(bn2 + 0 * GTILE) = ra0; *(uint4*)(bn2 + 0 * GTILE + 16) = ra1;
            *(uint4*)(bn2 + 1 * GTILE) = rc0; *(uint4*)(bn2 + 1 * GTILE + 16) = rc1;
            *(uint4*)(bn2 + 2 * GTILE) = rd0; *(uint4*)(bn2 + 2 * GTILE + 16) = rd1;
        }
        __syncthreads();
        cur ^= 1u;
    }

#pragma unroll
    for (int nt = 0; nt < 4; nt++) {
        int col = bn + wn * 32 + nt * 8 + (lane & 3) * 2;
        float bv0 = 0.0f, bv1 = 0.0f;
        if (bias0) { bv0 += bias0[col]; bv1 += bias0[col + 1]; }
        if (bias1) { bv0 += bias1[col]; bv1 += bias1[col + 1]; }
#pragma unroll
        for (int mi = 0; mi < 4; mi++) {
            int row = bm + wm * 64 + mi * 16 + (lane >> 2);
            *(__half2*)&C[(size_t)row * N + col] =
                __floats2half2_rn(acc[mi][nt][0] + bv0, acc[mi][nt][1] + bv1);
            *(__half2*)&C[(size_t)(row + 8) * N + col] =
                __floats2half2_rn(acc[mi][nt][2] + bv0, acc[mi][nt][3] + bv1);
        }
    }
}

// =====================================================================
// Attention GEMM (2-term) + fused tanh-dot epilogue -> g_attn
// =====================================================================
__global__ void __launch_bounds__(256) gemm_att(const __nv_bfloat16* __restrict__ Ahi,
                                                const __nv_bfloat16* __restrict__ Bhi,
                                                const __nv_bfloat16* __restrict__ Blo,
                                                const float* __restrict__ bias0,
                                                const float* __restrict__ vatt,
                                                int M, int K) {
    __shared__ __nv_bfloat16 sAhi[128 * ASTR];
    __shared__ __nv_bfloat16 sBhi[128 * ASTR], sBlo[128 * ASTR];
    __shared__ float sred[128 * 4];

    int tid = threadIdx.x;
    int warp = tid >> 5, lane = tid & 31;
    int wm = warp >> 2, wn = warp & 3;
    int bm = blockIdx.y * 128;

    int lrow0 = tid >> 1;
    int lseg0 = (tid & 1) * 2;
    const __nv_bfloat16* pAhi = Ahi + (size_t)(bm + lrow0) * K + lseg0 * 8;
    const __nv_bfloat16* pBhi = Bhi + (size_t)lrow0 * K + lseg0 * 8;
    const __nv_bfloat16* pBlo = Blo + (size_t)lrow0 * K + lseg0 * 8;

    float acc[4][4][4];
#pragma unroll
    for (int i = 0; i < 4; i++)
#pragma unroll
        for (int j = 0; j < 4; j++)
#pragma unroll
            for (int q = 0; q < 4; q++) acc[i][j][q] = 0.0f;

    uint32_t aAhi = smem_u32(sAhi);
    uint32_t aBhi = smem_u32(sBhi), aBlo = smem_u32(sBlo);

    uint32_t aRow = (uint32_t)(wm * 64 + (lane & 15));
    uint32_t aColHalf = (uint32_t)((lane >> 4) * 8);
    uint32_t g = (uint32_t)(lane >> 3);
    uint32_t bRow = (uint32_t)(wn * 32 + ((g >> 1) * 8) + (lane & 7));
    uint32_t bColHalf = (g & 1) * 8;

    uint4 ra0, ra1, rc0, rc1, rd0, rd1;
    ra0 = *(const uint4*)pAhi;       ra1 = *(const uint4*)(pAhi + 8);
    rc0 = *(const uint4*)pBhi;       rc1 = *(const uint4*)(pBhi + 8);
    rd0 = *(const uint4*)pBlo;       rd1 = *(const uint4*)(pBlo + 8);

    int nchunks = K >> 5;
    for (int c0 = 0; c0 < nchunks; c0++) {
        {
            uint4* d;
            d = (uint4*)&sAhi[lrow0 * ASTR + lseg0 * 8]; d[0] = ra0; d[1] = ra1;
            d = (uint4*)&sBhi[lrow0 * ASTR + lseg0 * 8]; d[0] = rc0; d[1] = rc1;
            d = (uint4*)&sBlo[lrow0 * ASTR + lseg0 * 8]; d[0] = rd0; d[1] = rd1;
        }
        __syncthreads();

        if (c0 + 1 < nchunks) {
            int kn = (c0 + 1) << 5;
            ra0 = *(const uint4*)(pAhi + kn);  ra1 = *(const uint4*)(pAhi + kn + 8);
            rc0 = *(const uint4*)(pBhi + kn);  rc1 = *(const uint4*)(pBhi + kn + 8);
            rd0 = *(const uint4*)(pBlo + kn);  rd1 = *(const uint4*)(pBlo + kn + 8);
        }

#pragma unroll
        for (int ko = 0; ko < 32; ko += 16) {
            uint32_t fahi[4][4], fbhi[2][4], fblo[2][4];
#pragma unroll
            for (int mi = 0; mi < 4; mi++) {
                uint32_t off = ((aRow + mi * 16) * ASTR + ko + aColHalf) * 2;
                ldmat4(fahi[mi], aAhi + off);
            }
#pragma unroll
            for (int np = 0; np < 2; np++) {
                uint32_t off = ((bRow + np * 16) * ASTR + ko + bColHalf) * 2;
                ldmat4(fbhi[np], aBhi + off);
                ldmat4(fblo[np], aBlo + off);
            }
#pragma unroll
            for (int mi = 0; mi < 4; mi++) {
#pragma unroll
                for (int nt = 0; nt < 4; nt++) {
                    int np = nt >> 1, hf = (nt & 1) * 2;
                    uint32_t bh[2] = { fbhi[np][hf], fbhi[np][hf + 1] };
                    uint32_t bl[2] = { fblo[np][hf], fblo[np][hf + 1] };
                    mma16816(acc[mi][nt], fahi[mi], bh);
                    mma16816(acc[mi][nt], fahi[mi], bl);
                }
            }
        }
        __syncthreads();
    }

    float rsum[4][2];
#pragma unroll
    for (int mi = 0; mi < 4; mi++) { rsum[mi][0] = 0.0f; rsum[mi][1] = 0.0f; }
#pragma unroll
    for (int nt = 0; nt < 4; nt++) {
        int col = wn * 32 + nt * 8 + (lane & 3) * 2;
        float b0v = bias0[col], b1v = bias0[col + 1];
        float v0 = vatt[col], v1 = vatt[col + 1];
#pragma unroll
        for (int mi = 0; mi < 4; mi++) {
            rsum[mi][0] += ftanh(acc[mi][nt][0] + b0v) * v0
                         + ftanh(acc[mi][nt][1] + b1v) * v1;
            rsum[mi][1] += ftanh(acc[mi][nt][2] + b0v) * v0
                         + ftanh(acc[mi][nt][3] + b1v) * v1;
        }
    }
#pragma unroll
    for (int off = 1; off <= 2; off <<= 1) {
#pragma unroll
        for (int mi = 0; mi < 4; mi++) {
            rsum[mi][0] += __shfl_xor_sync(0xffffffffu, rsum[mi][0], off);
            rsum[mi][1] += __shfl_xor_sync(0xffffffffu, rsum[mi][1], off);
        }
    }
    if ((lane & 3) == 0) {
#pragma unroll
        for (int mi = 0; mi < 4; mi++) {
            int r0 = wm * 64 + mi * 16 + (lane >> 2);
            sred[r0 * 4 + wn] = rsum[mi][0];
            sred[(r0 + 8) * 4 + wn] = rsum[mi][1];
        }
    }
    __syncthreads();
    if (tid < 128) {
        g_attn[bm + tid] = sred[tid * 4] + sred[tid * 4 + 1] +
                           sred[tid * 4 + 2] + sred[tid * 4 + 3];
    }
}

// =====================================================================
// LSTM recurrence, 512 threads, FFMA2; xp read as fp16.
// =====================================================================
#define WPAD 132
#define REC_SMEM ((256 * WPAD + 512 + 512 + 4096) * 4)
__global__ void __launch_bounds__(512, 1) lstm_rec(const __half* __restrict__ xp,
                                                   const float* __restrict__ Whh,
                                                   float* __restrict__ houtf,
                                                   __nv_bfloat16* __restrict__ hhi) {
    extern __shared__ float sm[];
    float* w_s = sm;
    float* h_s = w_s + 256 * WPAD;
    float* c_s = h_s + 512;
    float* gp  = c_s + 512;
    int tid = threadIdx.x;
    int t8 = tid & 255, kh = tid >> 8;
    int k0 = kh * 64;
    int b0 = blockIdx.x * 4;

    ulonglong2 w1r[16];
    const float* wg = Whh + (size_t)(256 + t8) * HH + k0;
#pragma unroll
    for (int i = 0; i < 16; i++) w1r[i] = __ldg((const ulonglong2*)(wg + 4 * i));

    for (int l = tid; l < 256 * HH; l += 512) {
        int r = l >> 7, k = l & 127;
        w_s[r * WPAD + k] = Whh[r * HH + k];
    }
    if (tid < 512) { h_s[tid] = 0.0f; c_s[tid] = 0.0f; }
    __syncthreads();

    const float* w0p = &w_s[t8 * WPAD + k0];

    int xrow = t8 + kh * 256;
    float xc[4];
    {
        const __half* xpt = xp + (size_t)b0 * GG + xrow;
#pragma unroll
        for (int bb = 0; bb < 4; bb++) xc[bb] = __half2float(xpt[bb * GG]);
    }

    for (int t = 0; t < TT; t++) {
        unsigned long long a0v[4], a1v[4];
#pragma unroll
        for (int bb = 0; bb < 4; bb++) {
            a0v[bb] = packf2((kh == 0) ? xc[bb] : 0.0f, 0.0f);
            a1v[bb] = packf2((kh == 0) ? 0.0f : xc[bb], 0.0f);
        }

        if (t + 1 < TT) {
            const __half* xn = xp + ((size_t)(t + 1) * BB + b0) * GG + xrow;
#pragma unroll
            for (int bb = 0; bb < 4; bb++) xc[bb] = __half2float(xn[bb * GG]);
        }

#pragma unroll
        for (int k4 = 0; k4 < 16; k4++) {
            ulonglong2 w0 = *(const ulonglong2*)(w0p + 4 * k4);
            ulonglong2 w1 = w1r[k4];
            int k = k0 + 4 * k4;
#pragma unroll
            for (int bb = 0; bb < 4; bb++) {
                ulonglong2 hb = *(const ulonglong2*)&h_s[bb * HH + k];
                ffma2(a0v[bb], hb.x, w0.x);
                ffma2(a0v[bb], hb.y, w0.y);
                ffma2(a1v[bb], hb.x, w1.x);
                ffma2(a1v[bb], hb.y, w1.y);
            }
        }
#pragma unroll
        for (int bb = 0; bb < 4; bb++) {
            float2 s0 = unpackf2(a0v[bb]);
            float2 s1 = unpackf2(a1v[bb]);
            gp[(kh * 4 + bb) * 512 + t8]       = s0.x + s0.y;
            gp[(kh * 4 + bb) * 512 + 256 + t8] = s1.x + s1.y;
        }
        __syncthreads();

        {
            int bb = tid >> 7, hh = tid & 127;
            const float* g0 = &gp[bb * 512];
            const float* g1 = &gp[(4 + bb) * 512];
            float gi = g0[hh]       + g1[hh];
            float gf = g0[128 + hh] + g1[128 + hh];
            float gc = g0[256 + hh] + g1[256 + hh];
            float go = g0[384 + hh] + g1[384 + hh];
            float cc = fsig(gf) * c_s[tid] + fsig(gi) * ftanh(gc);
            float h  = fsig(go) * ftanh(cc);
            c_s[tid] = cc;
            h_s[tid] = h;
            size_t oi = ((size_t)t * BB + b0 + bb) * HH + hh;
            hhi[oi] = __float2bfloat16(h);
            if (houtf) houtf[oi] = h;
        }
        __syncthreads();
    }
}

// ---------------- softmax + pool ----------------
__global__ void __launch_bounds__(128) pool_kernel() {
    int b = blockIdx.x;
    int tid = threadIdx.x;
    __shared__ float wt[TT];
    __shared__ float red[128];
    float a = (tid < TT) ? g_attn[tid * BB + b] : -1e30f;
    red[tid] = a;
    __syncthreads();
    for (int s = 64; s; s >>= 1) {
        if (tid < s) red[tid] = fmaxf(red[tid], red[tid + s]);
        __syncthreads();
    }
    float mx = red[0];
    __syncthreads();
    float e = (tid < TT) ? __expf(a - mx) : 0.0f;
    red[tid] = e;
    __syncthreads();
    for (int s = 64; s; s >>= 1) {
        if (tid < s) red[tid] += red[tid + s];
        __syncthreads();
    }
    float inv = __fdividef(1.0f, red[0]);
    if (tid < TT) wt[tid] = e * inv;
    __syncthreads();
    float acc = 0.0f;
#pragma unroll 4
    for (int t = 0; t < TT; t++)
        acc += wt[t] * g_h2[((size_t)t * BB + b) * HH + tid];
    g_pooled[b * HH + tid] = acc;
}

// ---------------- head ----------------
__global__ void __launch_bounds__(64) head_kernel(const float* __restrict__ W1,
                                                  const float* __restrict__ b1,
                                                  const float* __restrict__ W2,
                                                  const float* __restrict__ b2,
                                                  float* __restrict__ out) {
    int b = blockIdx.x;
    int tid = threadIdx.x;
    __shared__ float p[HH];
    __shared__ float hdn[64];
    for (int l = tid; l < HH; l += 64) p[l] = g_pooled[b * HH + l];
    __syncthreads();
    float acc = b1[tid];
#pragma unroll 8
    for (int k = 0; k < HH; k++) acc += p[k] * W1[tid * HH + k];
    hdn[tid] = acc;
    __syncthreads();
    if (tid < NC) {
        float o = b2[tid];
#pragma unroll
        for (int k = 0; k < 64; k++) o += hdn[k] * W2[tid * 64 + k];
        out[b * NC + tid] = o;
    }
}

// ---------------- host ----------------
extern "C" void kernel_launch(void* const* d_in, const int* in_sizes, int n_in,
                              void* d_out, int out_size) {
    const float* x      = (const float*)d_in[0];
    const float* conv_w = (const float*)d_in[1];
    const float* conv_b = (const float*)d_in[2];
    const float* Wih0   = (const float*)d_in[3];
    const float* Whh0   = (const float*)d_in[4];
    const float* bih0   = (const float*)d_in[5];
    const float* bhh0   = (const float*)d_in[6];
    const float* Wih1   = (const float*)d_in[7];
    const float* Whh1   = (const float*)d_in[8];
    const float* bih1   = (const float*)d_in[9];
    const float* bhh1   = (const float*)d_in[10];
    const float* W_att  = (const float*)d_in[11];
    const float* b_att  = (const float*)d_in[12];
    const float* v_att  = (const float*)d_in[13];
    const float* W1     = (const float*)d_in[14];
    const float* b1     = (const float*)d_in[15];
    const float* W2     = (const float*)d_in[16];
    const float* b2     = (const float*)d_in[17];
    float* out = (float*)d_out;

    float *h2_p;
    __half* xp_p;
    __nv_bfloat16 *Ahi_p, *W0hi_p, *W0lo_p, *W1hi_p, *W1lo_p, *Wahi_p, *Walo_p;
    cudaGetSymbolAddress((void**)&xp_p,    g_xp);
    cudaGetSymbolAddress((void**)&h2_p,    g_h2);
    cudaGetSymbolAddress((void**)&Ahi_p,  g_Ahi);
    cudaGetSymbolAddress((void**)&W0hi_p, g_W0hi);
    cudaGetSymbolAddress((void**)&W0lo_p, g_W0lo);
    cudaGetSymbolAddress((void**)&W1hi_p, g_W1hi);
    cudaGetSymbolAddress((void**)&W1lo_p, g_W1lo);
    cudaGetSymbolAddress((void**)&Wahi_p, g_Wahi);
    cudaGetSymbolAddress((void**)&Walo_p, g_Walo);

    cudaFuncSetAttribute(conv_kernel, cudaFuncAttributeMaxDynamicSharedMemorySize,
                         812 * 40 * 4);
    cudaFuncSetAttribute(lstm_rec, cudaFuncAttributeMaxDynamicSharedMemorySize,
                         REC_SMEM);
    cudaFuncSetAttribute(gemm_mma, cudaFuncAttributeMaxDynamicSharedMemorySize,
                         GSMEM);

    const int M = TT * BB;   // 51200

    // launches #1-#3: weight prep
    prep_a<<<(N4_W0 + 255) / 256, 256>>>(Wih0);
    prep_b<<<(N4_W1 + 255) / 256, 256>>>(Wih1);
    prep_c<<<(N4_WA + 255) / 256, 256>>>(W_att);

    // launch #4: conv (round-12 form, 1 CTA/image)
    conv_kernel<<<BB, 256, 812 * 40 * 4>>>(x, conv_w, conv_b);

    gemm_mma<<<dim3(GG / 128, M / 128), 256, GSMEM>>>(Ahi_p, W0hi_p, W0lo_p,
                                                      bih0, bhh0, xp_p, M, GG, FF);
    lstm_rec<<<BB / 4, 512, REC_SMEM>>>(xp_p, Whh0, nullptr, Ahi_p);

    gemm_mma<<<dim3(GG / 128, M / 128), 256, GSMEM>>>(Ahi_p, W1hi_p, W1lo_p,
                                                      bih1, bhh1, xp_p, M, GG, HH);
    lstm_rec<<<BB / 4, 512, REC_SMEM>>>(xp_p, Whh1, h2_p, Ahi_p);

    gemm_att<<<dim3(1, M / 128), 256>>>(Ahi_p, Wahi_p, Walo_p,
                                        b_att, v_att, M, HH);
    pool_kernel<<<BB, 128>>>();
    head_kernel<<<BB, 64>>>(W1, b1, W2, b2, out);
}

// round 16
// speedup vs baseline: 1.5862x; 1.5862x over previous
#include <cuda_runtime.h>
#include <cuda_bf16.h>
#include <math.h>
#include <stdint.h>

// ---------------- problem constants ----------------
#define TT   100
#define BB   512
#define WW   18
#define CC   32
#define FF   576
#define HH   128
#define GG   512
#define NC   12

// ---------------- device scratch ----------------
__device__ float g_xp  [TT * BB * GG];
__device__ float g_h2  [TT * BB * HH];
__device__ float g_attn [TT * BB];
__device__ float g_pooled[BB * HH];
__device__ __nv_bfloat16 g_Ahi[TT * BB * FF];
__device__ __nv_bfloat16 g_W0hi[GG * FF], g_W0lo[GG * FF];
__device__ __nv_bfloat16 g_W1hi[GG * HH], g_W1lo[GG * HH];
__device__ __nv_bfloat16 g_Wahi[HH * HH], g_Walo[HH * HH];

// fast activations (EX2/RCP approx)
__device__ __forceinline__ float ftanh(float x) {
    float xc = fminf(fmaxf(x, -9.0f), 9.0f);
    float t = __expf(2.0f * xc);
    return __fdividef(t - 1.0f, t + 1.0f);
}
__device__ __forceinline__ float fsig(float x) {
    return __fdividef(1.0f, 1.0f + __expf(-x));
}

// packed f32x2 helpers
__device__ __forceinline__ void ffma2(unsigned long long& acc, unsigned long long a,
                                      unsigned long long b) {
    asm("fma.rn.f32x2 %0, %1, %2, %0;" : "+l"(acc) : "l"(a), "l"(b));
}
__device__ __forceinline__ unsigned long long packf2(float lo, float hi) {
    unsigned long long r;
    asm("mov.b64 %0, {%1,%2};" : "=l"(r) : "f"(lo), "f"(hi));
    return r;
}
__device__ __forceinline__ float2 unpackf2(unsigned long long v) {
    float2 r;
    asm("mov.b64 {%0,%1}, %2;" : "=f"(r.x), "=f"(r.y) : "l"(v));
    return r;
}

__device__ __forceinline__ uint32_t smem_u32(const void* p) {
    uint32_t a;
    asm("{ .reg .u64 t; cvta.to.shared.u64 t, %1; cvt.u32.u64 %0, t; }" : "=r"(a) : "l"(p));
    return a;
}
__device__ __forceinline__ void ldmat4(uint32_t* r, uint32_t addr) {
    asm volatile("ldmatrix.sync.aligned.m8n8.x4.shared.b16 {%0,%1,%2,%3}, [%4];"
                 : "=r"(r[0]), "=r"(r[1]), "=r"(r[2]), "=r"(r[3]) : "r"(addr));
}
__device__ __forceinline__ void mma16816(float* c, const uint32_t* a, const uint32_t* b) {
    asm volatile(
        "mma.sync.aligned.m16n8k16.row.col.f32.bf16.bf16.f32 "
        "{%0,%1,%2,%3}, {%4,%5,%6,%7}, {%8,%9}, {%0,%1,%2,%3};"
        : "+f"(c[0]), "+f"(c[1]), "+f"(c[2]), "+f"(c[3])
        : "r"(a[0]), "r"(a[1]), "r"(a[2]), "r"(a[3]), "r"(b[0]), "r"(b[1]));
}
__device__ __forceinline__ void split1(float v, __nv_bfloat16& h, __nv_bfloat16& l) {
    h = __float2bfloat16(v);
    l = __float2bfloat16(v - __bfloat162float(h));
}

// =====================================================================
// Weight prep: 3 launches
// =====================================================================
#define N4_W0 (GG * FF / 4)
#define N4_W1 (GG * HH / 4)
#define N4_WA (HH * HH / 4)
__global__ void __launch_bounds__(256) prep_a(const float* __restrict__ Wih0) {
    int i = blockIdx.x * 256 + threadIdx.x;
    if (i >= N4_W0) return;
    float4 v = ((const float4*)Wih0)[i];
    __nv_bfloat16 h0, h1, h2, h3, l0, l1, l2, l3;
    split1(v.x, h0, l0); split1(v.y, h1, l1);
    split1(v.z, h2, l2); split1(v.w, h3, l3);
    ((__nv_bfloat162*)g_W0hi)[2 * i]     = __nv_bfloat162(h0, h1);
    ((__nv_bfloat162*)g_W0hi)[2 * i + 1] = __nv_bfloat162(h2, h3);
    ((__nv_bfloat162*)g_W0lo)[2 * i]     = __nv_bfloat162(l0, l1);
    ((__nv_bfloat162*)g_W0lo)[2 * i + 1] = __nv_bfloat162(l2, l3);
}
__global__ void __launch_bounds__(256) prep_b(const float* __restrict__ Wih1) {
    int i = blockIdx.x * 256 + threadIdx.x;
    if (i >= N4_W1) return;
    float4 v = ((const float4*)Wih1)[i];
    __nv_bfloat16 h0, h1, h2, h3, l0, l1, l2, l3;
    split1(v.x, h0, l0); split1(v.y, h1, l1);
    split1(v.z, h2, l2); split1(v.w, h3, l3);
    ((__nv_bfloat162*)g_W1hi)[2 * i]     = __nv_bfloat162(h0, h1);
    ((__nv_bfloat162*)g_W1hi)[2 * i + 1] = __nv_bfloat162(h2, h3);
    ((__nv_bfloat162*)g_W1lo)[2 * i]     = __nv_bfloat162(l0, l1);
    ((__nv_bfloat162*)g_W1lo)[2 * i + 1] = __nv_bfloat162(l2, l3);
}
__global__ void __launch_bounds__(256) prep_c(const float* __restrict__ W_att) {
    int i = blockIdx.x * 256 + threadIdx.x;
    if (i >= N4_WA) return;
    int j = i * 4;
#pragma unroll
    for (int e = 0; e < 4; e++) {
        int idx = j + e;
        int c = idx >> 7, r = idx & 127;
        float v = W_att[r * HH + c];
        __nv_bfloat16 h, l;
        split1(v, h, l);
        g_Wahi[idx] = h;
        g_Walo[idx] = l;
    }
}

// =====================================================================
// Conv: one block per image, 127KB smem, minBlocks=1 (no reg cap/spill).
// =====================================================================
__global__ void __launch_bounds__(256, 1) conv_kernel(const float* __restrict__ x,
                                                      const float* __restrict__ cw,
                                                      const float* __restrict__ cb) {
    extern __shared__ float s_img[];
    int b = blockIdx.x;
    int tid = threadIdx.x;
    int wid = tid >> 5, lane = tid & 31;
    int c = lane;

    const float4* src = (const float4*)(x + (size_t)b * 812 * 40);
    float4* dst = (float4*)s_img;
    for (int i = tid; i < 812 * 10; i += 256) dst[i] = src[i];

    float wr[100];
#pragma unroll
    for (int i = 0; i < 100; i++) wr[i] = __ldg(&cw[c * 100 + i]);
    float bv = __ldg(&cb[c]);
    __syncthreads();

    for (int p = wid; p < 50; p += 8) {
        int base_row = 16 * p;
        float acc[2][18];
#pragma unroll
        for (int w = 0; w < 18; w++) { acc[0][w] = bv; acc[1][w] = bv; }
#pragma unroll
        for (int rr = 0; rr < 28; rr++) {
            const float4* prow4 = (const float4*)&s_img[(base_row + rr) * 40];
#pragma unroll
            for (int j4 = 0; j4 < 10; j4++) {
                float4 pj = prow4[j4];
                float pv4[4] = {pj.x, pj.y, pj.z, pj.w};
#pragma unroll
                for (int e = 0; e < 4; e++) {
                    int j = 4 * j4 + e;
                    float pv = pv4[e];
#pragma unroll
                    for (int kw = 0; kw < 5; kw++) {
                        int d = j - kw;
                        if (d >= 0 && (d & 1) == 0) {
                            int w = d >> 1;
                            if (w < 18) {
                                if (rr < 20) acc[0][w] += wr[rr * 5 + kw] * pv;
                                if (rr >= 8) acc[1][w] += wr[(rr - 8) * 5 + kw] * pv;
                            }
                        }
                    }
                }
            }
        }
#pragma unroll
        for (int ts = 0; ts < 2; ts++) {
            int t = 2 * p + ts;
            size_t base = ((size_t)t * BB + b) * FF + c;
#pragma unroll
            for (int w = 0; w < 18; w++)
                g_Ahi[base + w * 32] = __float2bfloat16(fmaxf(acc[ts][w], 0.0f));
        }
    }
}

// =====================================================================
// 2-term GEMM: C = Ahi@(Bhi+Blo)^T + bias. mma.sync, double-buffered.
// =====================================================================
#define ASTR 40
#define GTILE (128 * ASTR * 2)
#define GBUF  (3 * GTILE)
#define GSMEM (2 * GBUF)

__global__ void __launch_bounds__(256) gemm_mma(const __nv_bfloat16* __restrict__ Ahi,
                                                const __nv_bfloat16* __restrict__ Bhi,
                                                const __nv_bfloat16* __restrict__ Blo,
                                                const float* __restrict__ bias0,
                                                const float* __restrict__ bias1,
                                                float* __restrict__ C,
                                                int M, int N, int K) {
    extern __shared__ char gsm[];
    int tid = threadIdx.x;
    int warp = tid >> 5, lane = tid & 31;
    int wm = warp >> 2, wn = warp & 3;
    int bm = blockIdx.y * 128, bn = blockIdx.x * 128;

    int lrow0 = tid >> 1;
    int lseg0 = (tid & 1) * 2;
    const __nv_bfloat16* pAhi = Ahi + (size_t)(bm + lrow0) * K + lseg0 * 8;
    const __nv_bfloat16* pBhi = Bhi + (size_t)(bn + lrow0) * K + lseg0 * 8;
    const __nv_bfloat16* pBlo = Blo + (size_t)(bn + lrow0) * K + lseg0 * 8;

    float acc[4][4][4];
#pragma unroll
    for (int i = 0; i < 4; i++)
#pragma unroll
        for (int j = 0; j < 4; j++)
#pragma unroll
            for (int q = 0; q < 4; q++) acc[i][j][q] = 0.0f;

    uint32_t sb = smem_u32(gsm);
    uint32_t stoff = (uint32_t)(lrow0 * ASTR + lseg0 * 8) * 2;

    uint32_t aRow = (uint32_t)(wm * 64 + (lane & 15));
    uint32_t aColHalf = (uint32_t)((lane >> 4) * 8);
    uint32_t g = (uint32_t)(lane >> 3);
    uint32_t bRow = (uint32_t)(wn * 32 + ((g >> 1) * 8) + (lane & 7));
    uint32_t bColHalf = (g & 1) * 8;

    uint4 ra0, ra1, rc0, rc1, rd0, rd1;
    ra0 = *(const uint4*)pAhi;       ra1 = *(const uint4*)(pAhi + 8);
    rc0 = *(const uint4*)pBhi;       rc1 = *(const uint4*)(pBhi + 8);
    rd0 = *(const uint4*)pBlo;       rd1 = *(const uint4*)(pBlo + 8);

    {
        char* b0 = gsm + stoff;
        *(uint4*)(b0 + 0 * GTILE) = ra0; *(uint4*)(b0 + 0 * GTILE + 16) = ra1;
        *(uint4*)(b0 + 1 * GTILE) = rc0; *(uint4*)(b0 + 1 * GTILE + 16) = rc1;
        *(uint4*)(b0 + 2 * GTILE) = rd0; *(uint4*)(b0 + 2 * GTILE + 16) = rd1;
    }
    __syncthreads();

    int nchunks = K >> 5;
    uint32_t cur = 0;
    for (int c0 = 0; c0 < nchunks; c0++) {
        bool more = (c0 + 1) < nchunks;
        if (more) {
            int kn = (c0 + 1) << 5;
            ra0 = *(const uint4*)(pAhi + kn);  ra1 = *(const uint4*)(pAhi + kn + 8);
            rc0 = *(const uint4*)(pBhi + kn);  rc1 = *(const uint4*)(pBhi + kn + 8);
            rd0 = *(const uint4*)(pBlo + kn);  rd1 = *(const uint4*)(pBlo + kn + 8);
        }

        uint32_t base = sb + cur * GBUF;
#pragma unroll
        for (int ko = 0; ko < 32; ko += 16) {
            uint32_t fahi[4][4], fbhi[2][4], fblo[2][4];
#pragma unroll
            for (int mi = 0; mi < 4; mi++) {
                uint32_t off = ((aRow + mi * 16) * ASTR + ko + aColHalf) * 2;
                ldmat4(fahi[mi], base + 0 * GTILE + off);
            }
#pragma unroll
            for (int np = 0; np < 2; np++) {
                uint32_t off = ((bRow + np * 16) * ASTR + ko + bColHalf) * 2;
                ldmat4(fbhi[np], base + 1 * GTILE + off);
                ldmat4(fblo[np], base + 2 * GTILE + off);
            }
#pragma unroll
            for (int mi = 0; mi < 4; mi++) {
#pragma unroll
                for (int nt = 0; nt < 4; nt++) {
                    int np = nt >> 1, hf = (nt & 1) * 2;
                    uint32_t bh[2] = { fbhi[np][hf], fbhi[np][hf + 1] };
                    uint32_t bl[2] = { fblo[np][hf], fblo[np][hf + 1] };
                    mma16816(acc[mi][nt], fahi[mi], bh);
                    mma16816(acc[mi][nt], fahi[mi], bl);
                }
            }
        }

        if (more) {
            char* bn2 = gsm + (cur ^ 1u) * GBUF + stoff;
            *(uint4*)(bn2 + 0 * GTILE) = ra0; *(uint4*)(bn2 + 0 * GTILE + 16) = ra1;
            *(uint4*)(bn2 + 1 * GTILE) = rc0; *(uint4*)(bn2 + 1 * GTILE + 16) = rc1;
            *(uint4*)(bn2 + 2 * GTILE) = rd0; *(uint4*)(bn2 + 2 * GTILE + 16) = rd1;
        }
        __syncthreads();
        cur ^= 1u;
    }

#pragma unroll
    for (int nt = 0; nt < 4; nt++) {
        int col = bn + wn * 32 + nt * 8 + (lane & 3) * 2;
        float bv0 = 0.0f, bv1 = 0.0f;
        if (bias0) { bv0 += bias0[col]; bv1 += bias0[col + 1]; }
        if (bias1) { bv0 += bias1[col]; bv1 += bias1[col + 1]; }
#pragma unroll
        for (int mi = 0; mi < 4; mi++) {
            int row = bm + wm * 64 + mi * 16 + (lane >> 2);
            float2 v0 = make_float2(acc[mi][nt][0] + bv0, acc[mi][nt][1] + bv1);
            float2 v1 = make_float2(acc[mi][nt][2] + bv0, acc[mi][nt][3] + bv1);
            *(float2*)&C[(size_t)row * N + col] = v0;
            *(float2*)&C[(size_t)(row + 8) * N + col] = v1;
        }
    }
}

// =====================================================================
// Attention GEMM (2-term) + fused tanh-dot epilogue -> g_attn
// =====================================================================
__global__ void __launch_bounds__(256) gemm_att(const __nv_bfloat16* __restrict__ Ahi,
                                                const __nv_bfloat16* __restrict__ Bhi,
                                                const __nv_bfloat16* __restrict__ Blo,
                                                const float* __restrict__ bias0,
                                                const float* __restrict__ vatt,
                                                int M, int K) {
    __shared__ __nv_bfloat16 sAhi[128 * ASTR];
    __shared__ __nv_bfloat16 sBhi[128 * ASTR], sBlo[128 * ASTR];
    __shared__ float sred[128 * 4];

    int tid = threadIdx.x;
    int warp = tid >> 5, lane = tid & 31;
    int wm = warp >> 2, wn = warp & 3;
    int bm = blockIdx.y * 128;

    int lrow0 = tid >> 1;
    int lseg0 = (tid & 1) * 2;
    const __nv_bfloat16* pAhi = Ahi + (size_t)(bm + lrow0) * K + lseg0 * 8;
    const __nv_bfloat16* pBhi = Bhi + (size_t)lrow0 * K + lseg0 * 8;
    const __nv_bfloat16* pBlo = Blo + (size_t)lrow0 * K + lseg0 * 8;

    float acc[4][4][4];
#pragma unroll
    for (int i = 0; i < 4; i++)
#pragma unroll
        for (int j = 0; j < 4; j++)
#pragma unroll
            for (int q = 0; q < 4; q++) acc[i][j][q] = 0.0f;

    uint32_t aAhi = smem_u32(sAhi);
    uint32_t aBhi = smem_u32(sBhi), aBlo = smem_u32(sBlo);

    uint32_t aRow = (uint32_t)(wm * 64 + (lane & 15));
    uint32_t aColHalf = (uint32_t)((lane >> 4) * 8);
    uint32_t g = (uint32_t)(lane >> 3);
    uint32_t bRow = (uint32_t)(wn * 32 + ((g >> 1) * 8) + (lane & 7));
    uint32_t bColHalf = (g & 1) * 8;

    uint4 ra0, ra1, rc0, rc1, rd0, rd1;
    ra0 = *(const uint4*)pAhi;       ra1 = *(const uint4*)(pAhi + 8);
    rc0 = *(const uint4*)pBhi;       rc1 = *(const uint4*)(pBhi + 8);
    rd0 = *(const uint4*)pBlo;       rd1 = *(const uint4*)(pBlo + 8);

    int nchunks = K >> 5;
    for (int c0 = 0; c0 < nchunks; c0++) {
        {
            uint4* d;
            d = (uint4*)&sAhi[lrow0 * ASTR + lseg0 * 8]; d[0] = ra0; d[1] = ra1;
            d = (uint4*)&sBhi[lrow0 * ASTR + lseg0 * 8]; d[0] = rc0; d[1] = rc1;
            d = (uint4*)&sBlo[lrow0 * ASTR + lseg0 * 8]; d[0] = rd0; d[1] = rd1;
        }
        __syncthreads();

        if (c0 + 1 < nchunks) {
            int kn = (c0 + 1) << 5;
            ra0 = *(const uint4*)(pAhi + kn);  ra1 = *(const uint4*)(pAhi + kn + 8);
            rc0 = *(const uint4*)(pBhi + kn);  rc1 = *(const uint4*)(pBhi + kn + 8);
            rd0 = *(const uint4*)(pBlo + kn);  rd1 = *(const uint4*)(pBlo + kn + 8);
        }

#pragma unroll
        for (int ko = 0; ko < 32; ko += 16) {
            uint32_t fahi[4][4], fbhi[2][4], fblo[2][4];
#pragma unroll
            for (int mi = 0; mi < 4; mi++) {
                uint32_t off = ((aRow + mi * 16) * ASTR + ko + aColHalf) * 2;
                ldmat4(fahi[mi], aAhi + off);
            }
#pragma unroll
            for (int np = 0; np < 2; np++) {
                uint32_t off = ((bRow + np * 16) * ASTR + ko + bColHalf) * 2;
                ldmat4(fbhi[np], aBhi + off);
                ldmat4(fblo[np], aBlo + off);
            }
#pragma unroll
            for (int mi = 0; mi < 4; mi++) {
#pragma unroll
                for (int nt = 0; nt < 4; nt++) {
                    int np = nt >> 1, hf = (nt & 1) * 2;
                    uint32_t bh[2] = { fbhi[np][hf], fbhi[np][hf + 1] };
                    uint32_t bl[2] = { fblo[np][hf], fblo[np][hf + 1] };
                    mma16816(acc[mi][nt], fahi[mi], bh);
                    mma16816(acc[mi][nt], fahi[mi], bl);
                }
            }
        }
        __syncthreads();
    }

    float rsum[4][2];
#pragma unroll
    for (int mi = 0; mi < 4; mi++) { rsum[mi][0] = 0.0f; rsum[mi][1] = 0.0f; }
#pragma unroll
    for (int nt = 0; nt < 4; nt++) {
        int col = wn * 32 + nt * 8 + (lane & 3) * 2;
        float b0v = bias0[col], b1v = bias0[col + 1];
        float v0 = vatt[col], v1 = vatt[col + 1];
#pragma unroll
        for (int mi = 0; mi < 4; mi++) {
            rsum[mi][0] += ftanh(acc[mi][nt][0] + b0v) * v0
                         + ftanh(acc[mi][nt][1] + b1v) * v1;
            rsum[mi][1] += ftanh(acc[mi][nt][2] + b0v) * v0
                         + ftanh(acc[mi][nt][3] + b1v) * v1;
        }
    }
#pragma unroll
    for (int off = 1; off <= 2; off <<= 1) {
#pragma unroll
        for (int mi = 0; mi < 4; mi++) {
            rsum[mi][0] += __shfl_xor_sync(0xffffffffu, rsum[mi][0], off);
            rsum[mi][1] += __shfl_xor_sync(0xffffffffu, rsum[mi][1], off);
        }
    }
    if ((lane & 3) == 0) {
#pragma unroll
        for (int mi = 0; mi < 4; mi++) {
            int r0 = wm * 64 + mi * 16 + (lane >> 2);
            sred[r0 * 4 + wn] = rsum[mi][0];
            sred[(r0 + 8) * 4 + wn] = rsum[mi][1];
        }
    }
    __syncthreads();
    if (tid < 128) {
        g_attn[bm + tid] = sred[tid * 4] + sred[tid * 4 + 1] +
                           sred[tid * 4 + 2] + sred[tid * 4 + 3];
    }
}

// =====================================================================
// LSTM recurrence, 512 threads, FFMA2; epilogue writes bf16 hi only.
// =====================================================================
#define WPAD 132
#define REC_SMEM ((256 * WPAD + 512 + 512 + 4096) * 4)
__global__ void __launch_bounds__(512, 1) lstm_rec(const float* __restrict__ xp,
                                                   const float* __restrict__ Whh,
                                                   float* __restrict__ houtf,
                                                   __nv_bfloat16* __restrict__ hhi) {
    extern __shared__ float sm[];
    float* w_s = sm;
    float* h_s = w_s + 256 * WPAD;
    float* c_s = h_s + 512;
    float* gp  = c_s + 512;
    int tid = threadIdx.x;
    int t8 = tid & 255, kh = tid >> 8;
    int k0 = kh * 64;
    int b0 = blockIdx.x * 4;

    ulonglong2 w1r[16];
    const float* wg = Whh + (size_t)(256 + t8) * HH + k0;
#pragma unroll
    for (int i = 0; i < 16; i++) w1r[i] = __ldg((const ulonglong2*)(wg + 4 * i));

    for (int l = tid; l < 256 * HH; l += 512) {
        int r = l >> 7, k = l & 127;
        w_s[r * WPAD + k] = Whh[r * HH + k];
    }
    if (tid < 512) { h_s[tid] = 0.0f; c_s[tid] = 0.0f; }
    __syncthreads();

    const float* w0p = &w_s[t8 * WPAD + k0];

    int xrow = t8 + kh * 256;
    float xc[4];
    {
        const float* xpt = xp + (size_t)b0 * GG + xrow;
#pragma unroll
        for (int bb = 0; bb < 4; bb++) xc[bb] = xpt[bb * GG];
    }

    for (int t = 0; t < TT; t++) {
        unsigned long long a0v[4], a1v[4];
#pragma unroll
        for (int bb = 0; bb < 4; bb++) {
            a0v[bb] = packf2((kh == 0) ? xc[bb] : 0.0f, 0.0f);
            a1v[bb] = packf2((kh == 0) ? 0.0f : xc[bb], 0.0f);
        }

        if (t + 1 < TT) {
            const float* xn = xp + ((size_t)(t + 1) * BB + b0) * GG + xrow;
#pragma unroll
            for (int bb = 0; bb < 4; bb++) xc[bb] = xn[bb * GG];
        }

#pragma unroll
        for (int k4 = 0; k4 < 16; k4++) {
            ulonglong2 w0 = *(const ulonglong2*)(w0p + 4 * k4);
            ulonglong2 w1 = w1r[k4];
            int k = k0 + 4 * k4;
#pragma unroll
            for (int bb = 0; bb < 4; bb++) {
                ulonglong2 hb = *(const ulonglong2*)&h_s[bb * HH + k];
                ffma2(a0v[bb], hb.x, w0.x);
                ffma2(a0v[bb], hb.y, w0.y);
                ffma2(a1v[bb], hb.x, w1.x);
                ffma2(a1v[bb], hb.y, w1.y);
            }
        }
#pragma unroll
        for (int bb = 0; bb < 4; bb++) {
            float2 s0 = unpackf2(a0v[bb]);
            float2 s1 = unpackf2(a1v[bb]);
            gp[(kh * 4 + bb) * 512 + t8]       = s0.x + s0.y;
            gp[(kh * 4 + bb) * 512 + 256 + t8] = s1.x + s1.y;
        }
        __syncthreads();

        {
            int bb = tid >> 7, hh = tid & 127;
            const float* g0 = &gp[bb * 512];
            const float* g1 = &gp[(4 + bb) * 512];
            float gi = g0[hh]       + g1[hh];
            float gf = g0[128 + hh] + g1[128 + hh];
            float gc = g0[256 + hh] + g1[256 + hh];
            float go = g0[384 + hh] + g1[384 + hh];
            float cc = fsig(gf) * c_s[tid] + fsig(gi) * ftanh(gc);
            float h  = fsig(go) * ftanh(cc);
            c_s[tid] = cc;
            h_s[tid] = h;
            size_t oi = ((size_t)t * BB + b0 + bb) * HH + hh;
            hhi[oi] = __float2bfloat16(h);
            if (houtf) houtf[oi] = h;
        }
        __syncthreads();
    }
}

// ---------------- softmax + pool ----------------
__global__ void __launch_bounds__(128) pool_kernel() {
    int b = blockIdx.x;
    int tid = threadIdx.x;
    __shared__ float wt[TT];
    __shared__ float red[128];
    float a = (tid < TT) ? g_attn[tid * BB + b] : -1e30f;
    red[tid] = a;
    __syncthreads();
    for (int s = 64; s; s >>= 1) {
        if (tid < s) red[tid] = fmaxf(red[tid], red[tid + s]);
        __syncthreads();
    }
    float mx = red[0];
    __syncthreads();
    float e = (tid < TT) ? __expf(a - mx) : 0.0f;
    red[tid] = e;
    __syncthreads();
    for (int s = 64; s; s >>= 1) {
        if (tid < s) red[tid] += red[tid + s];
        __syncthreads();
    }
    float inv = __fdividef(1.0f, red[0]);
    if (tid < TT) wt[tid] = e * inv;
    __syncthreads();
    float acc = 0.0f;
#pragma unroll 4
    for (int t = 0; t < TT; t++)
        acc += wt[t] * g_h2[((size_t)t * BB + b) * HH + tid];
    g_pooled[b * HH + tid] = acc;
}

// ---------------- head ----------------
__global__ void __launch_bounds__(64) head_kernel(const float* __restrict__ W1,
                                                  const float* __restrict__ b1,
                                                  const float* __restrict__ W2,
                                                  const float* __restrict__ b2,
                                                  float* __restrict__ out) {
    int b = blockIdx.x;
    int tid = threadIdx.x;
    __shared__ float p[HH];
    __shared__ float hdn[64];
    for (int l = tid; l < HH; l += 64) p[l] = g_pooled[b * HH + l];
    __syncthreads();
    float acc = b1[tid];
#pragma unroll 8
    for (int k = 0; k < HH; k++) acc += p[k] * W1[tid * HH + k];
    hdn[tid] = acc;
    __syncthreads();
    if (tid < NC) {
        float o = b2[tid];
#pragma unroll
        for (int k = 0; k < 64; k++) o += hdn[k] * W2[tid * 64 + k];
        out[b * NC + tid] = o;
    }
}

// ---------------- host ----------------
extern "C" void kernel_launch(void* const* d_in, const int* in_sizes, int n_in,
                              void* d_out, int out_size) {
    const float* x      = (const float*)d_in[0];
    const float* conv_w = (const float*)d_in[1];
    const float* conv_b = (const float*)d_in[2];
    const float* Wih0   = (const float*)d_in[3];
    const float* Whh0   = (const float*)d_in[4];
    const float* bih0   = (const float*)d_in[5];
    const float* bhh0   = (const float*)d_in[6];
    const float* Wih1   = (const float*)d_in[7];
    const float* Whh1   = (const float*)d_in[8];
    const float* bih1   = (const float*)d_in[9];
    const float* bhh1   = (const float*)d_in[10];
    const float* W_att  = (const float*)d_in[11];
    const float* b_att  = (const float*)d_in[12];
    const float* v_att  = (const float*)d_in[13];
    const float* W1     = (const float*)d_in[14];
    const float* b1     = (const float*)d_in[15];
    const float* W2     = (const float*)d_in[16];
    const float* b2     = (const float*)d_in[17];
    float* out = (float*)d_out;

    float *xp_p, *h2_p;
    __nv_bfloat16 *Ahi_p, *W0hi_p, *W0lo_p, *W1hi_p, *W1lo_p, *Wahi_p, *Walo_p;
    cudaGetSymbolAddress((void**)&xp_p,    g_xp);
    cudaGetSymbolAddress((void**)&h2_p,    g_h2);
    cudaGetSymbolAddress((void**)&Ahi_p,  g_Ahi);
    cudaGetSymbolAddress((void**)&W0hi_p, g_W0hi);
    cudaGetSymbolAddress((void**)&W0lo_p, g_W0lo);
    cudaGetSymbolAddress((void**)&W1hi_p, g_W1hi);
    cudaGetSymbolAddress((void**)&W1lo_p, g_W1lo);
    cudaGetSymbolAddress((void**)&Wahi_p, g_Wahi);
    cudaGetSymbolAddress((void**)&Walo_p, g_Walo);

    cudaFuncSetAttribute(conv_kernel, cudaFuncAttributeMaxDynamicSharedMemorySize,
                         812 * 40 * 4);
    cudaFuncSetAttribute(lstm_rec, cudaFuncAttributeMaxDynamicSharedMemorySize,
                         REC_SMEM);
    cudaFuncSetAttribute(gemm_mma, cudaFuncAttributeMaxDynamicSharedMemorySize,
                         GSMEM);

    const int M = TT * BB;   // 51200

    // launches #1-#3: weight prep
    prep_a<<<(N4_W0 + 255) / 256, 256>>>(Wih0);
    prep_b<<<(N4_W1 + 255) / 256, 256>>>(Wih1);
    prep_c<<<(N4_WA + 255) / 256, 256>>>(W_att);

    // launch #4: conv
    conv_kernel<<<BB, 256, 812 * 40 * 4>>>(x, conv_w, conv_b);

    gemm_mma<<<dim3(GG / 128, M / 128), 256, GSMEM>>>(Ahi_p, W0hi_p, W0lo_p,
                                                      bih0, bhh0, xp_p, M, GG, FF);
    lstm_rec<<<BB / 4, 512, REC_SMEM>>>(xp_p, Whh0, nullptr, Ahi_p);

    gemm_mma<<<dim3(GG / 128, M / 128), 256, GSMEM>>>(Ahi_p, W1hi_p, W1lo_p,
                                                      bih1, bhh1, xp_p, M, GG, HH);
    lstm_rec<<<BB / 4, 512, REC_SMEM>>>(xp_p, Whh1, h2_p, Ahi_p);

    gemm_att<<<dim3(1, M / 128), 256>>>(Ahi_p, Wahi_p, Walo_p,
                                        b_att, v_att, M, HH);
    pool_kernel<<<BB, 128>>>();
    head_kernel<<<BB, 64>>>(W1, b1, W2, b2, out);
}

// round 17
// speedup vs baseline: 2.0990x; 1.3233x over previous
#include <cuda_runtime.h>
#include <cuda_bf16.h>
#include <math.h>
#include <stdint.h>

// ---------------- problem constants ----------------
#define TT   100
#define BB   512
#define WW   18
#define CC   32
#define FF   576
#define HH   128
#define GG   512
#define NC   12

// ---------------- device scratch ----------------
__device__ float g_xp  [TT * BB * GG];
__device__ float g_h2  [TT * BB * HH];
__device__ float g_attn [TT * BB];
__device__ float g_pooled[BB * HH];
__device__ __nv_bfloat16 g_Ahi[TT * BB * FF];
__device__ __nv_bfloat16 g_W0hi[GG * FF], g_W0lo[GG * FF];
__device__ __nv_bfloat16 g_W1hi[GG * HH], g_W1lo[GG * HH];
__device__ __nv_bfloat16 g_Wahi[HH * HH], g_Walo[HH * HH];

// fast activations (EX2/RCP approx)
__device__ __forceinline__ float ftanh(float x) {
    float xc = fminf(fmaxf(x, -9.0f), 9.0f);
    float t = __expf(2.0f * xc);
    return __fdividef(t - 1.0f, t + 1.0f);
}
__device__ __forceinline__ float fsig(float x) {
    return __fdividef(1.0f, 1.0f + __expf(-x));
}

// packed f32x2 helpers
__device__ __forceinline__ void ffma2(unsigned long long& acc, unsigned long long a,
                                      unsigned long long b) {
    asm("fma.rn.f32x2 %0, %1, %2, %0;" : "+l"(acc) : "l"(a), "l"(b));
}
__device__ __forceinline__ unsigned long long packf2(float lo, float hi) {
    unsigned long long r;
    asm("mov.b64 %0, {%1,%2};" : "=l"(r) : "f"(lo), "f"(hi));
    return r;
}
__device__ __forceinline__ float2 unpackf2(unsigned long long v) {
    float2 r;
    asm("mov.b64 {%0,%1}, %2;" : "=f"(r.x), "=f"(r.y) : "l"(v));
    return r;
}

__device__ __forceinline__ uint32_t smem_u32(const void* p) {
    uint32_t a;
    asm("{ .reg .u64 t; cvta.to.shared.u64 t, %1; cvt.u32.u64 %0, t; }" : "=r"(a) : "l"(p));
    return a;
}
__device__ __forceinline__ void ldmat4(uint32_t* r, uint32_t addr) {
    asm volatile("ldmatrix.sync.aligned.m8n8.x4.shared.b16 {%0,%1,%2,%3}, [%4];"
                 : "=r"(r[0]), "=r"(r[1]), "=r"(r[2]), "=r"(r[3]) : "r"(addr));
}
__device__ __forceinline__ void mma16816(float* c, const uint32_t* a, const uint32_t* b) {
    asm volatile(
        "mma.sync.aligned.m16n8k16.row.col.f32.bf16.bf16.f32 "
        "{%0,%1,%2,%3}, {%4,%5,%6,%7}, {%8,%9}, {%0,%1,%2,%3};"
        : "+f"(c[0]), "+f"(c[1]), "+f"(c[2]), "+f"(c[3])
        : "r"(a[0]), "r"(a[1]), "r"(a[2]), "r"(a[3]), "r"(b[0]), "r"(b[1]));
}
__device__ __forceinline__ void split1(float v, __nv_bfloat16& h, __nv_bfloat16& l) {
    h = __float2bfloat16(v);
    l = __float2bfloat16(v - __bfloat162float(h));
}

// =====================================================================
// Weight prep: 3 launches
// =====================================================================
#define N4_W0 (GG * FF / 4)
#define N4_W1 (GG * HH / 4)
#define N4_WA (HH * HH / 4)
__global__ void __launch_bounds__(256) prep_a(const float* __restrict__ Wih0) {
    int i = blockIdx.x * 256 + threadIdx.x;
    if (i >= N4_W0) return;
    float4 v = ((const float4*)Wih0)[i];
    __nv_bfloat16 h0, h1, h2, h3, l0, l1, l2, l3;
    split1(v.x, h0, l0); split1(v.y, h1, l1);
    split1(v.z, h2, l2); split1(v.w, h3, l3);
    ((__nv_bfloat162*)g_W0hi)[2 * i]     = __nv_bfloat162(h0, h1);
    ((__nv_bfloat162*)g_W0hi)[2 * i + 1] = __nv_bfloat162(h2, h3);
    ((__nv_bfloat162*)g_W0lo)[2 * i]     = __nv_bfloat162(l0, l1);
    ((__nv_bfloat162*)g_W0lo)[2 * i + 1] = __nv_bfloat162(l2, l3);
}
__global__ void __launch_bounds__(256) prep_b(const float* __restrict__ Wih1) {
    int i = blockIdx.x * 256 + threadIdx.x;
    if (i >= N4_W1) return;
    float4 v = ((const float4*)Wih1)[i];
    __nv_bfloat16 h0, h1, h2, h3, l0, l1, l2, l3;
    split1(v.x, h0, l0); split1(v.y, h1, l1);
    split1(v.z, h2, l2); split1(v.w, h3, l3);
    ((__nv_bfloat162*)g_W1hi)[2 * i]     = __nv_bfloat162(h0, h1);
    ((__nv_bfloat162*)g_W1hi)[2 * i + 1] = __nv_bfloat162(h2, h3);
    ((__nv_bfloat162*)g_W1lo)[2 * i]     = __nv_bfloat162(l0, l1);
    ((__nv_bfloat162*)g_W1lo)[2 * i + 1] = __nv_bfloat162(l2, l3);
}
__global__ void __launch_bounds__(256) prep_c(const float* __restrict__ W_att) {
    int i = blockIdx.x * 256 + threadIdx.x;
    if (i >= N4_WA) return;
    int j = i * 4;
#pragma unroll
    for (int e = 0; e < 4; e++) {
        int idx = j + e;
        int c = idx >> 7, r = idx & 127;
        float v = W_att[r * HH + c];
        __nv_bfloat16 h, l;
        split1(v, h, l);
        g_Wahi[idx] = h;
        g_Walo[idx] = l;
    }
}

// =====================================================================
// Conv: TWO blocks per image (time-axis halves), 66KB smem each.
// __launch_bounds__(256, 1) is LOAD-BEARING: it prevents the 64-reg
// cap that spilled wr[100] in round 14. regs ~114 -> 2 CTAs/SM fit
// (smem 2x66KB, regs 2x256x114 = 58K < 64K), 1024 CTAs over 148 SMs.
// Arithmetic bit-identical to the 1-CTA version.
// =====================================================================
#define CONV_ROWS 412
#define CONV_SMEM (CONV_ROWS * 40 * 4)
__global__ void __launch_bounds__(256, 1) conv_kernel(const float* __restrict__ x,
                                                      const float* __restrict__ cw,
                                                      const float* __restrict__ cb) {
    extern __shared__ float s_img[];   // [412][40]
    int b = blockIdx.x;
    int hy = blockIdx.y;               // 0 or 1
    int r0 = 400 * hy;
    int tid = threadIdx.x;
    int wid = tid >> 5, lane = tid & 31;
    int c = lane;

    const float4* src = (const float4*)(x + ((size_t)b * 812 + r0) * 40);
    float4* dst = (float4*)s_img;
    for (int i = tid; i < CONV_ROWS * 10; i += 256) dst[i] = src[i];

    float wr[100];
#pragma unroll
    for (int i = 0; i < 100; i++) wr[i] = __ldg(&cw[c * 100 + i]);
    float bv = __ldg(&cb[c]);
    __syncthreads();

    for (int p = hy * 25 + wid; p < hy * 25 + 25; p += 8) {
        int base_row = 16 * p - r0;     // local row within the 412-row slab
        float acc[2][18];
#pragma unroll
        for (int w = 0; w < 18; w++) { acc[0][w] = bv; acc[1][w] = bv; }
#pragma unroll
        for (int rr = 0; rr < 28; rr++) {
            const float4* prow4 = (const float4*)&s_img[(base_row + rr) * 40];
#pragma unroll
            for (int j4 = 0; j4 < 10; j4++) {
                float4 pj = prow4[j4];
                float pv4[4] = {pj.x, pj.y, pj.z, pj.w};
#pragma unroll
                for (int e = 0; e < 4; e++) {
                    int j = 4 * j4 + e;
                    float pv = pv4[e];
#pragma unroll
                    for (int kw = 0; kw < 5; kw++) {
                        int d = j - kw;
                        if (d >= 0 && (d & 1) == 0) {
                            int w = d >> 1;
                            if (w < 18) {
                                if (rr < 20) acc[0][w] += wr[rr * 5 + kw] * pv;
                                if (rr >= 8) acc[1][w] += wr[(rr - 8) * 5 + kw] * pv;
                            }
                        }
                    }
                }
            }
        }
#pragma unroll
        for (int ts = 0; ts < 2; ts++) {
            int t = 2 * p + ts;
            size_t base = ((size_t)t * BB + b) * FF + c;
#pragma unroll
            for (int w = 0; w < 18; w++)
                g_Ahi[base + w * 32] = __float2bfloat16(fmaxf(acc[ts][w], 0.0f));
        }
    }
}

// =====================================================================
// 2-term GEMM: C = Ahi@(Bhi+Blo)^T + bias. mma.sync, double-buffered.
// =====================================================================
#define ASTR 40
#define GTILE (128 * ASTR * 2)
#define GBUF  (3 * GTILE)
#define GSMEM (2 * GBUF)

__global__ void __launch_bounds__(256) gemm_mma(const __nv_bfloat16* __restrict__ Ahi,
                                                const __nv_bfloat16* __restrict__ Bhi,
                                                const __nv_bfloat16* __restrict__ Blo,
                                                const float* __restrict__ bias0,
                                                const float* __restrict__ bias1,
                                                float* __restrict__ C,
                                                int M, int N, int K) {
    extern __shared__ char gsm[];
    int tid = threadIdx.x;
    int warp = tid >> 5, lane = tid & 31;
    int wm = warp >> 2, wn = warp & 3;
    int bm = blockIdx.y * 128, bn = blockIdx.x * 128;

    int lrow0 = tid >> 1;
    int lseg0 = (tid & 1) * 2;
    const __nv_bfloat16* pAhi = Ahi + (size_t)(bm + lrow0) * K + lseg0 * 8;
    const __nv_bfloat16* pBhi = Bhi + (size_t)(bn + lrow0) * K + lseg0 * 8;
    const __nv_bfloat16* pBlo = Blo + (size_t)(bn + lrow0) * K + lseg0 * 8;

    float acc[4][4][4];
#pragma unroll
    for (int i = 0; i < 4; i++)
#pragma unroll
        for (int j = 0; j < 4; j++)
#pragma unroll
            for (int q = 0; q < 4; q++) acc[i][j][q] = 0.0f;

    uint32_t sb = smem_u32(gsm);
    uint32_t stoff = (uint32_t)(lrow0 * ASTR + lseg0 * 8) * 2;

    uint32_t aRow = (uint32_t)(wm * 64 + (lane & 15));
    uint32_t aColHalf = (uint32_t)((lane >> 4) * 8);
    uint32_t g = (uint32_t)(lane >> 3);
    uint32_t bRow = (uint32_t)(wn * 32 + ((g >> 1) * 8) + (lane & 7));
    uint32_t bColHalf = (g & 1) * 8;

    uint4 ra0, ra1, rc0, rc1, rd0, rd1;
    ra0 = *(const uint4*)pAhi;       ra1 = *(const uint4*)(pAhi + 8);
    rc0 = *(const uint4*)pBhi;       rc1 = *(const uint4*)(pBhi + 8);
    rd0 = *(const uint4*)pBlo;       rd1 = *(const uint4*)(pBlo + 8);

    {
        char* b0 = gsm + stoff;
        *(uint4*)(b0 + 0 * GTILE) = ra0; *(uint4*)(b0 + 0 * GTILE + 16) = ra1;
        *(uint4*)(b0 + 1 * GTILE) = rc0; *(uint4*)(b0 + 1 * GTILE + 16) = rc1;
        *(uint4*)(b0 + 2 * GTILE) = rd0; *(uint4*)(b0 + 2 * GTILE + 16) = rd1;
    }
    __syncthreads();

    int nchunks = K >> 5;
    uint32_t cur = 0;
    for (int c0 = 0; c0 < nchunks; c0++) {
        bool more = (c0 + 1) < nchunks;
        if (more) {
            int kn = (c0 + 1) << 5;
            ra0 = *(const uint4*)(pAhi + kn);  ra1 = *(const uint4*)(pAhi + kn + 8);
            rc0 = *(const uint4*)(pBhi + kn);  rc1 = *(const uint4*)(pBhi + kn + 8);
            rd0 = *(const uint4*)(pBlo + kn);  rd1 = *(const uint4*)(pBlo + kn + 8);
        }

        uint32_t base = sb + cur * GBUF;
#pragma unroll
        for (int ko = 0; ko < 32; ko += 16) {
            uint32_t fahi[4][4], fbhi[2][4], fblo[2][4];
#pragma unroll
            for (int mi = 0; mi < 4; mi++) {
                uint32_t off = ((aRow + mi * 16) * ASTR + ko + aColHalf) * 2;
                ldmat4(fahi[mi], base + 0 * GTILE + off);
            }
#pragma unroll
            for (int np = 0; np < 2; np++) {
                uint32_t off = ((bRow + np * 16) * ASTR + ko + bColHalf) * 2;
                ldmat4(fbhi[np], base + 1 * GTILE + off);
                ldmat4(fblo[np], base + 2 * GTILE + off);
            }
#pragma unroll
            for (int mi = 0; mi < 4; mi++) {
#pragma unroll
                for (int nt = 0; nt < 4; nt++) {
                    int np = nt >> 1, hf = (nt & 1) * 2;
                    uint32_t bh[2] = { fbhi[np][hf], fbhi[np][hf + 1] };
                    uint32_t bl[2] = { fblo[np][hf], fblo[np][hf + 1] };
                    mma16816(acc[mi][nt], fahi[mi], bh);
                    mma16816(acc[mi][nt], fahi[mi], bl);
                }
            }
        }

        if (more) {
            char* bn2 = gsm + (cur ^ 1u) * GBUF + stoff;
            *(uint4*)(bn2 + 0 * GTILE) = ra0; *(uint4*)(bn2 + 0 * GTILE + 16) = ra1;
            *(uint4*)(bn2 + 1 * GTILE) = rc0; *(uint4*)(bn2 + 1 * GTILE + 16) = rc1;
            *(uint4*)(bn2 + 2 * GTILE) = rd0; *(uint4*)(bn2 + 2 * GTILE + 16) = rd1;
        }
        __syncthreads();
        cur ^= 1u;
    }

#pragma unroll
    for (int nt = 0; nt < 4; nt++) {
        int col = bn + wn * 32 + nt * 8 + (lane & 3) * 2;
        float bv0 = 0.0f, bv1 = 0.0f;
        if (bias0) { bv0 += bias0[col]; bv1 += bias0[col + 1]; }
        if (bias1) { bv0 += bias1[col]; bv1 += bias1[col + 1]; }
#pragma unroll
        for (int mi = 0; mi < 4; mi++) {
            int row = bm + wm * 64 + mi * 16 + (lane >> 2);
            float2 v0 = make_float2(acc[mi][nt][0] + bv0, acc[mi][nt][1] + bv1);
            float2 v1 = make_float2(acc[mi][nt][2] + bv0, acc[mi][nt][3] + bv1);
            *(float2*)&C[(size_t)row * N + col] = v0;
            *(float2*)&C[(size_t)(row + 8) * N + col] = v1;
        }
    }
}

// =====================================================================
// Attention GEMM (2-term) + fused tanh-dot epilogue -> g_attn
// =====================================================================
__global__ void __launch_bounds__(256) gemm_att(const __nv_bfloat16* __restrict__ Ahi,
                                                const __nv_bfloat16* __restrict__ Bhi,
                                                const __nv_bfloat16* __restrict__ Blo,
                                                const float* __restrict__ bias0,
                                                const float* __restrict__ vatt,
                                                int M, int K) {
    __shared__ __nv_bfloat16 sAhi[128 * ASTR];
    __shared__ __nv_bfloat16 sBhi[128 * ASTR], sBlo[128 * ASTR];
    __shared__ float sred[128 * 4];

    int tid = threadIdx.x;
    int warp = tid >> 5, lane = tid & 31;
    int wm = warp >> 2, wn = warp & 3;
    int bm = blockIdx.y * 128;

    int lrow0 = tid >> 1;
    int lseg0 = (tid & 1) * 2;
    const __nv_bfloat16* pAhi = Ahi + (size_t)(bm + lrow0) * K + lseg0 * 8;
    const __nv_bfloat16* pBhi = Bhi + (size_t)lrow0 * K + lseg0 * 8;
    const __nv_bfloat16* pBlo = Blo + (size_t)lrow0 * K + lseg0 * 8;

    float acc[4][4][4];
#pragma unroll
    for (int i = 0; i < 4; i++)
#pragma unroll
        for (int j = 0; j < 4; j++)
#pragma unroll
            for (int q = 0; q < 4; q++) acc[i][j][q] = 0.0f;

    uint32_t aAhi = smem_u32(sAhi);
    uint32_t aBhi = smem_u32(sBhi), aBlo = smem_u32(sBlo);

    uint32_t aRow = (uint32_t)(wm * 64 + (lane & 15));
    uint32_t aColHalf = (uint32_t)((lane >> 4) * 8);
    uint32_t g = (uint32_t)(lane >> 3);
    uint32_t bRow = (uint32_t)(wn * 32 + ((g >> 1) * 8) + (lane & 7));
    uint32_t bColHalf = (g & 1) * 8;

    uint4 ra0, ra1, rc0, rc1, rd0, rd1;
    ra0 = *(const uint4*)pAhi;       ra1 = *(const uint4*)(pAhi + 8);
    rc0 = *(const uint4*)pBhi;       rc1 = *(const uint4*)(pBhi + 8);
    rd0 = *(const uint4*)pBlo;       rd1 = *(const uint4*)(pBlo + 8);

    int nchunks = K >> 5;
    for (int c0 = 0; c0 < nchunks; c0++) {
        {
            uint4* d;
            d = (uint4*)&sAhi[lrow0 * ASTR + lseg0 * 8]; d[0] = ra0; d[1] = ra1;
            d = (uint4*)&sBhi[lrow0 * ASTR + lseg0 * 8]; d[0] = rc0; d[1] = rc1;
            d = (uint4*)&sBlo[lrow0 * ASTR + lseg0 * 8]; d[0] = rd0; d[1] = rd1;
        }
        __syncthreads();

        if (c0 + 1 < nchunks) {
            int kn = (c0 + 1) << 5;
            ra0 = *(const uint4*)(pAhi + kn);  ra1 = *(const uint4*)(pAhi + kn + 8);
            rc0 = *(const uint4*)(pBhi + kn);  rc1 = *(const uint4*)(pBhi + kn + 8);
            rd0 = *(const uint4*)(pBlo + kn);  rd1 = *(const uint4*)(pBlo + kn + 8);
        }

#pragma unroll
        for (int ko = 0; ko < 32; ko += 16) {
            uint32_t fahi[4][4], fbhi[2][4], fblo[2][4];
#pragma unroll
            for (int mi = 0; mi < 4; mi++) {
                uint32_t off = ((aRow + mi * 16) * ASTR + ko + aColHalf) * 2;
                ldmat4(fahi[mi], aAhi + off);
            }
#pragma unroll
            for (int np = 0; np < 2; np++) {
                uint32_t off = ((bRow + np * 16) * ASTR + ko + bColHalf) * 2;
                ldmat4(fbhi[np], aBhi + off);
                ldmat4(fblo[np], aBlo + off);
            }
#pragma unroll
            for (int mi = 0; mi < 4; mi++) {
#pragma unroll
                for (int nt = 0; nt < 4; nt++) {
                    int np = nt >> 1, hf = (nt & 1) * 2;
                    uint32_t bh[2] = { fbhi[np][hf], fbhi[np][hf + 1] };
                    uint32_t bl[2] = { fblo[np][hf], fblo[np][hf + 1] };
                    mma16816(acc[mi][nt], fahi[mi], bh);
                    mma16816(acc[mi][nt], fahi[mi], bl);
                }
            }
        }
        __syncthreads();
    }

    float rsum[4][2];
#pragma unroll
    for (int mi = 0; mi < 4; mi++) { rsum[mi][0] = 0.0f; rsum[mi][1] = 0.0f; }
#pragma unroll
    for (int nt = 0; nt < 4; nt++) {
        int col = wn * 32 + nt * 8 + (lane & 3) * 2;
        float b0v = bias0[col], b1v = bias0[col + 1];
        float v0 = vatt[col], v1 = vatt[col + 1];
#pragma unroll
        for (int mi = 0; mi < 4; mi++) {
            rsum[mi][0] += ftanh(acc[mi][nt][0] + b0v) * v0
                         + ftanh(acc[mi][nt][1] + b1v) * v1;
            rsum[mi][1] += ftanh(acc[mi][nt][2] + b0v) * v0
                         + ftanh(acc[mi][nt][3] + b1v) * v1;
        }
    }
#pragma unroll
    for (int off = 1; off <= 2; off <<= 1) {
#pragma unroll
        for (int mi = 0; mi < 4; mi++) {
            rsum[mi][0] += __shfl_xor_sync(0xffffffffu, rsum[mi][0], off);
            rsum[mi][1] += __shfl_xor_sync(0xffffffffu, rsum[mi][1], off);
        }
    }
    if ((lane & 3) == 0) {
#pragma unroll
        for (int mi = 0; mi < 4; mi++) {
            int r0 = wm * 64 + mi * 16 + (lane >> 2);
            sred[r0 * 4 + wn] = rsum[mi][0];
            sred[(r0 + 8) * 4 + wn] = rsum[mi][1];
        }
    }
    __syncthreads();
    if (tid < 128) {
        g_attn[bm + tid] = sred[tid * 4] + sred[tid * 4 + 1] +
                           sred[tid * 4 + 2] + sred[tid * 4 + 3];
    }
}

// =====================================================================
// LSTM recurrence, 512 threads, FFMA2; epilogue writes bf16 hi only.
// =====================================================================
#define WPAD 132
#define REC_SMEM ((256 * WPAD + 512 + 512 + 4096) * 4)
__global__ void __launch_bounds__(512, 1) lstm_rec(const float* __restrict__ xp,
                                                   const float* __restrict__ Whh,
                                                   float* __restrict__ houtf,
                                                   __nv_bfloat16* __restrict__ hhi) {
    extern __shared__ float sm[];
    float* w_s = sm;
    float* h_s = w_s + 256 * WPAD;
    float* c_s = h_s + 512;
    float* gp  = c_s + 512;
    int tid = threadIdx.x;
    int t8 = tid & 255, kh = tid >> 8;
    int k0 = kh * 64;
    int b0 = blockIdx.x * 4;

    ulonglong2 w1r[16];
    const float* wg = Whh + (size_t)(256 + t8) * HH + k0;
#pragma unroll
    for (int i = 0; i < 16; i++) w1r[i] = __ldg((const ulonglong2*)(wg + 4 * i));

    for (int l = tid; l < 256 * HH; l += 512) {
        int r = l >> 7, k = l & 127;
        w_s[r * WPAD + k] = Whh[r * HH + k];
    }
    if (tid < 512) { h_s[tid] = 0.0f; c_s[tid] = 0.0f; }
    __syncthreads();

    const float* w0p = &w_s[t8 * WPAD + k0];

    int xrow = t8 + kh * 256;
    float xc[4];
    {
        const float* xpt = xp + (size_t)b0 * GG + xrow;
#pragma unroll
        for (int bb = 0; bb < 4; bb++) xc[bb] = xpt[bb * GG];
    }

    for (int t = 0; t < TT; t++) {
        unsigned long long a0v[4], a1v[4];
#pragma unroll
        for (int bb = 0; bb < 4; bb++) {
            a0v[bb] = packf2((kh == 0) ? xc[bb] : 0.0f, 0.0f);
            a1v[bb] = packf2((kh == 0) ? 0.0f : xc[bb], 0.0f);
        }

        if (t + 1 < TT) {
            const float* xn = xp + ((size_t)(t + 1) * BB + b0) * GG + xrow;
#pragma unroll
            for (int bb = 0; bb < 4; bb++) xc[bb] = xn[bb * GG];
        }

#pragma unroll
        for (int k4 = 0; k4 < 16; k4++) {
            ulonglong2 w0 = *(const ulonglong2*)(w0p + 4 * k4);
            ulonglong2 w1 = w1r[k4];
            int k = k0 + 4 * k4;
#pragma unroll
            for (int bb = 0; bb < 4; bb++) {
                ulonglong2 hb = *(const ulonglong2*)&h_s[bb * HH + k];
                ffma2(a0v[bb], hb.x, w0.x);
                ffma2(a0v[bb], hb.y, w0.y);
                ffma2(a1v[bb], hb.x, w1.x);
                ffma2(a1v[bb], hb.y, w1.y);
            }
        }
#pragma unroll
        for (int bb = 0; bb < 4; bb++) {
            float2 s0 = unpackf2(a0v[bb]);
            float2 s1 = unpackf2(a1v[bb]);
            gp[(kh * 4 + bb) * 512 + t8]       = s0.x + s0.y;
            gp[(kh * 4 + bb) * 512 + 256 + t8] = s1.x + s1.y;
        }
        __syncthreads();

        {
            int bb = tid >> 7, hh = tid & 127;
            const float* g0 = &gp[bb * 512];
            const float* g1 = &gp[(4 + bb) * 512];
            float gi = g0[hh]       + g1[hh];
            float gf = g0[128 + hh] + g1[128 + hh];
            float gc = g0[256 + hh] + g1[256 + hh];
            float go = g0[384 + hh] + g1[384 + hh];
            float cc = fsig(gf) * c_s[tid] + fsig(gi) * ftanh(gc);
            float h  = fsig(go) * ftanh(cc);
            c_s[tid] = cc;
            h_s[tid] = h;
            size_t oi = ((size_t)t * BB + b0 + bb) * HH + hh;
            hhi[oi] = __float2bfloat16(h);
            if (houtf) houtf[oi] = h;
        }
        __syncthreads();
    }
}

// ---------------- softmax + pool ----------------
__global__ void __launch_bounds__(128) pool_kernel() {
    int b = blockIdx.x;
    int tid = threadIdx.x;
    __shared__ float wt[TT];
    __shared__ float red[128];
    float a = (tid < TT) ? g_attn[tid * BB + b] : -1e30f;
    red[tid] = a;
    __syncthreads();
    for (int s = 64; s; s >>= 1) {
        if (tid < s) red[tid] = fmaxf(red[tid], red[tid + s]);
        __syncthreads();
    }
    float mx = red[0];
    __syncthreads();
    float e = (tid < TT) ? __expf(a - mx) : 0.0f;
    red[tid] = e;
    __syncthreads();
    for (int s = 64; s; s >>= 1) {
        if (tid < s) red[tid] += red[tid + s];
        __syncthreads();
    }
    float inv = __fdividef(1.0f, red[0]);
    if (tid < TT) wt[tid] = e * inv;
    __syncthreads();
    float acc = 0.0f;
#pragma unroll 4
    for (int t = 0; t < TT; t++)
        acc += wt[t] * g_h2[((size_t)t * BB + b) * HH + tid];
    g_pooled[b * HH + tid] = acc;
}

// ---------------- head ----------------
__global__ void __launch_bounds__(64) head_kernel(const float* __restrict__ W1,
                                                  const float* __restrict__ b1,
                                                  const float* __restrict__ W2,
                                                  const float* __restrict__ b2,
                                                  float* __restrict__ out) {
    int b = blockIdx.x;
    int tid = threadIdx.x;
    __shared__ float p[HH];
    __shared__ float hdn[64];
    for (int l = tid; l < HH; l += 64) p[l] = g_pooled[b * HH + l];
    __syncthreads();
    float acc = b1[tid];
#pragma unroll 8
    for (int k = 0; k < HH; k++) acc += p[k] * W1[tid * HH + k];
    hdn[tid] = acc;
    __syncthreads();
    if (tid < NC) {
        float o = b2[tid];
#pragma unroll
        for (int k = 0; k < 64; k++) o += hdn[k] * W2[tid * 64 + k];
        out[b * NC + tid] = o;
    }
}

// ---------------- host ----------------
extern "C" void kernel_launch(void* const* d_in, const int* in_sizes, int n_in,
                              void* d_out, int out_size) {
    const float* x      = (const float*)d_in[0];
    const float* conv_w = (const float*)d_in[1];
    const float* conv_b = (const float*)d_in[2];
    const float* Wih0   = (const float*)d_in[3];
    const float* Whh0   = (const float*)d_in[4];
    const float* bih0   = (const float*)d_in[5];
    const float* bhh0   = (const float*)d_in[6];
    const float* Wih1   = (const float*)d_in[7];
    const float* Whh1   = (const float*)d_in[8];
    const float* bih1   = (const float*)d_in[9];
    const float* bhh1   = (const float*)d_in[10];
    const float* W_att  = (const float*)d_in[11];
    const float* b_att  = (const float*)d_in[12];
    const float* v_att  = (const float*)d_in[13];
    const float* W1     = (const float*)d_in[14];
    const float* b1     = (const float*)d_in[15];
    const float* W2     = (const float*)d_in[16];
    const float* b2     = (const float*)d_in[17];
    float* out = (float*)d_out;

    float *xp_p, *h2_p;
    __nv_bfloat16 *Ahi_p, *W0hi_p, *W0lo_p, *W1hi_p, *W1lo_p, *Wahi_p, *Walo_p;
    cudaGetSymbolAddress((void**)&xp_p,    g_xp);
    cudaGetSymbolAddress((void**)&h2_p,    g_h2);
    cudaGetSymbolAddress((void**)&Ahi_p,  g_Ahi);
    cudaGetSymbolAddress((void**)&W0hi_p, g_W0hi);
    cudaGetSymbolAddress((void**)&W0lo_p, g_W0lo);
    cudaGetSymbolAddress((void**)&W1hi_p, g_W1hi);
    cudaGetSymbolAddress((void**)&W1lo_p, g_W1lo);
    cudaGetSymbolAddress((void**)&Wahi_p, g_Wahi);
    cudaGetSymbolAddress((void**)&Walo_p, g_Walo);

    cudaFuncSetAttribute(conv_kernel, cudaFuncAttributeMaxDynamicSharedMemorySize,
                         CONV_SMEM);
    cudaFuncSetAttribute(lstm_rec, cudaFuncAttributeMaxDynamicSharedMemorySize,
                         REC_SMEM);
    cudaFuncSetAttribute(gemm_mma, cudaFuncAttributeMaxDynamicSharedMemorySize,
                         GSMEM);

    const int M = TT * BB;   // 51200

    // launches #1-#3: weight prep
    prep_a<<<(N4_W0 + 255) / 256, 256>>>(Wih0);
    prep_b<<<(N4_W1 + 255) / 256, 256>>>(Wih1);
    prep_c<<<(N4_WA + 255) / 256, 256>>>(W_att);

    // launch #4: conv (2 CTAs/image, spill-free)
    conv_kernel<<<dim3(BB, 2), 256, CONV_SMEM>>>(x, conv_w, conv_b);

    gemm_mma<<<dim3(GG / 128, M / 128), 256, GSMEM>>>(Ahi_p, W0hi_p, W0lo_p,
                                                      bih0, bhh0, xp_p, M, GG, FF);
    lstm_rec<<<BB / 4, 512, REC_SMEM>>>(xp_p, Whh0, nullptr, Ahi_p);

    gemm_mma<<<dim3(GG / 128, M / 128), 256, GSMEM>>>(Ahi_p, W1hi_p, W1lo_p,
                                                      bih1, bhh1, xp_p, M, GG, HH);
    lstm_rec<<<BB / 4, 512, REC_SMEM>>>(xp_p, Whh1, h2_p, Ahi_p);

    gemm_att<<<dim3(1, M / 128), 256>>>(Ahi_p, Wahi_p, Walo_p,
                                        b_att, v_att, M, HH);
    pool_kernel<<<BB, 128>>>();
    head_kernel<<<BB, 64>>>(W1, b1, W2, b2, out);
}